// round 13
// baseline (speedup 1.0000x reference)
#include <cuda_runtime.h>
#include <math.h>

#define B 8
#define N 2048
#define F 128
#define BN (B*N)
#define G2 64          // chunks per batch (scan)
#define C2 32          // rows per chunk (G2*C2 == N)

// ---------------- scratch (device globals) ----------------
__device__ float g_Wh[BN * F];          // 8 MB
__device__ float g_s1[BN];
__device__ float g_s2[BN];
__device__ float g_s2s[BN];             // sorted s2 per batch (ascending)
__device__ int   g_perm[BN];
__device__ float g_w[BN];               // exp(s2s - max) per batch
__device__ float g_S[BN * F];           // suffix sums of w_j * Wh[perm[j],:]
__device__ float g_Z[B * (N + 1)];      // scalar suffix sums of w
__device__ float g_mean[B * F];
__device__ float g_pw[B][G2][F];        // chunk partial weighted sums
__device__ float g_pm[B][G2][F];        // chunk partial plain sums (for mean)
__device__ int   g_flag[B * G2];        // partial-done flags (zeroed by sort_kernel)
__device__ int   g_flag2[B * G2];       // S-done flags       (zeroed by sort_kernel)

// ---- Kernel 1: Wh = h @ W^T. 128x128 tile, 8x8/thread, k-major smem ----
#define SST 132
__global__ void __launch_bounds__(256, 1) gemm_kernel(const float* __restrict__ A,
                                                      const float* __restrict__ W,
                                                      const float* __restrict__ a) {
    __shared__ float AsT[16][SST];
    __shared__ float Bs[16][SST];
    __shared__ float sa[256];
    const int m0 = blockIdx.x * 128;
    const int tid = threadIdx.x;
    sa[tid] = a[tid];

    const int ty = tid >> 4;
    const int tx = tid & 15;

    float acc[8][8];
#pragma unroll
    for (int i = 0; i < 8; i++)
#pragma unroll
        for (int j = 0; j < 8; j++) acc[i][j] = 0.f;

    for (int k0 = 0; k0 < 128; k0 += 16) {
#pragma unroll
        for (int s = 0; s < 2; s++) {
            int q = tid + s * 256;
            int m = q >> 2;
            int kq = (q & 3) * 4;
            float4 av = *(const float4*)(A + (size_t)(m0 + m) * 128 + k0 + kq);
            AsT[kq + 0][m] = av.x; AsT[kq + 1][m] = av.y;
            AsT[kq + 2][m] = av.z; AsT[kq + 3][m] = av.w;
            float4 wv = *(const float4*)(W + (size_t)m * 128 + k0 + kq);
            Bs[kq + 0][m] = wv.x; Bs[kq + 1][m] = wv.y;
            Bs[kq + 2][m] = wv.z; Bs[kq + 3][m] = wv.w;
        }
        __syncthreads();
#pragma unroll
        for (int kk = 0; kk < 16; kk++) {
            float af[8], bf[8];
            *(float4*)&af[0] = *(const float4*)&AsT[kk][ty * 8];
            *(float4*)&af[4] = *(const float4*)&AsT[kk][ty * 8 + 4];
            *(float4*)&bf[0] = *(const float4*)&Bs[kk][tx * 8];
            *(float4*)&bf[4] = *(const float4*)&Bs[kk][tx * 8 + 4];
#pragma unroll
            for (int i = 0; i < 8; i++)
#pragma unroll
                for (int j = 0; j < 8; j++) acc[i][j] = fmaf(af[i], bf[j], acc[i][j]);
        }
        __syncthreads();
    }
#pragma unroll
    for (int i = 0; i < 8; i++) {
        const int m = m0 + ty * 8 + i;
        float* crow = g_Wh + (size_t)m * 128 + tx * 8;
        *(float4*)(crow + 0) = make_float4(acc[i][0], acc[i][1], acc[i][2], acc[i][3]);
        *(float4*)(crow + 4) = make_float4(acc[i][4], acc[i][5], acc[i][6], acc[i][7]);
        float p1 = 0.f, p2 = 0.f;
#pragma unroll
        for (int j = 0; j < 8; j++) {
            p1 = fmaf(acc[i][j], sa[tx * 8 + j], p1);
            p2 = fmaf(acc[i][j], sa[128 + tx * 8 + j], p2);
        }
#pragma unroll
        for (int o = 8; o; o >>= 1) {
            p1 += __shfl_down_sync(0xFFFFFFFFu, p1, o, 16);
            p2 += __shfl_down_sync(0xFFFFFFFFu, p2, o, 16);
        }
        if (tx == 0) { g_s1[m] = p1; g_s2[m] = p2; }
    }
}

// register-resident bitonic compare-exchange via warp shuffle (j <= 16)
__device__ __forceinline__ void bshuf(float& kv, int& iv, unsigned ei, int k, int j) {
    float pk = __shfl_xor_sync(0xFFFFFFFFu, kv, j);
    int   pi = __shfl_xor_sync(0xFFFFFFFFu, iv, j);
    bool lower = ((ei & (unsigned)j) == 0u);
    bool up    = ((ei & (unsigned)k) == 0u);
    float kl = lower ? kv : pk;
    float kh = lower ? pk : kv;
    bool sw = up ? (kl > kh) : (kl < kh);
    if (sw) { kv = pk; iv = pi; }
}

// ---- Kernel 2: per-batch bitonic sort of s2 (hybrid smem/warp) + w=exp + Z suffix ----
__global__ void __launch_bounds__(1024) sort_kernel() {
    __shared__ float key[2048];
    __shared__ int   idx[2048];
    __shared__ float alt[2048];
    const int b = blockIdx.x;
    const int t = threadIdx.x;
    if (t < G2) g_flag[b * G2 + t] = 0;
    else if (t < 2 * G2) g_flag2[b * G2 + (t - G2)] = 0;

    float k0 = g_s2[b * N + t];
    float k1 = g_s2[b * N + t + 1024];
    int   i0 = t, i1 = t + 1024;
#pragma unroll
    for (int k = 2; k <= 32; k <<= 1)
#pragma unroll
        for (int j = k >> 1; j; j >>= 1) {
            bshuf(k0, i0, (unsigned)t, k, j);
            bshuf(k1, i1, (unsigned)(t + 1024), k, j);
        }
    key[t] = k0; idx[t] = i0;
    key[t + 1024] = k1; idx[t + 1024] = i1;
    __syncthreads();

    for (int k = 64; k <= 2048; k <<= 1) {
        for (int j = k >> 1; j >= 32; j >>= 1) {
            int i = ((t & ~(j - 1)) << 1) | (t & (j - 1));
            int p = i | j;
            bool up = ((i & k) == 0);
            float ki = key[i], kp = key[p];
            bool sw = up ? (ki > kp) : (ki < kp);
            if (sw) {
                key[i] = kp; key[p] = ki;
                int ii = idx[i]; idx[i] = idx[p]; idx[p] = ii;
            }
            __syncthreads();
        }
        k0 = key[t]; i0 = idx[t];
        k1 = key[t + 1024]; i1 = idx[t + 1024];
#pragma unroll
        for (int j = 16; j; j >>= 1) {
            bshuf(k0, i0, (unsigned)t, k, j);
            bshuf(k1, i1, (unsigned)(t + 1024), k, j);
        }
        key[t] = k0; idx[t] = i0;
        key[t + 1024] = k1; idx[t + 1024] = i1;
        __syncthreads();
    }

    g_s2s[b * N + t] = key[t];               g_perm[b * N + t] = idx[t];
    g_s2s[b * N + t + 1024] = key[t + 1024]; g_perm[b * N + t + 1024] = idx[t + 1024];

    const float mx = key[2047];
    __syncthreads();
    float w0 = expf(key[t] - mx);
    float w1 = expf(key[t + 1024] - mx);
    g_w[b * N + t] = w0;
    g_w[b * N + t + 1024] = w1;
    key[t] = w0; key[t + 1024] = w1;
    __syncthreads();
    float* src = key; float* dst = alt;
    for (int o = 1; o < 2048; o <<= 1) {
        dst[t]        = src[t] + ((t + o < 2048) ? src[t + o] : 0.f);
        dst[t + 1024] = src[t + 1024] + ((t + 1024 + o < 2048) ? src[t + 1024 + o] : 0.f);
        __syncthreads();
        float* tmp = src; src = dst; dst = tmp;
    }
    g_Z[b * (N + 1) + t] = src[t];
    g_Z[b * (N + 1) + t + 1024] = src[t + 1024];
    if (t == 0) g_Z[b * (N + 1) + 2048] = 0.f;
}

// ---- Kernel 3: partial + lookback + suffix scan + second lookback + output ----
// 512 blocks x 128 thr, 16.6KB smem: all co-resident in wave 1 -> spins are safe.
__global__ void __launch_bounds__(128) scan_out_kernel(float* __restrict__ out) {
    const int b = blockIdx.x >> 6;
    const int g = blockIdx.x & (G2 - 1);
    const int f = threadIdx.x;
    const int warp = f >> 5;
    const int lane = f & 31;
    __shared__ float rows[C2][F];
    __shared__ float sw[C2];
    __shared__ int   sp[C2];
    if (f < C2) {
        sw[f] = g_w[b * N + g * C2 + f];
        sp[f] = g_perm[b * N + g * C2 + f];
    }
    __syncthreads();
    const float* Whb = g_Wh + (size_t)b * N * 128;
    float accW = 0.f, accM = 0.f;
#pragma unroll 4
    for (int j = 0; j < C2; j++) {
        float x = Whb[(size_t)sp[j] * 128 + f];
        rows[j][f] = x;
        accW = fmaf(sw[j], x, accW);
        accM += x;
    }
    g_pw[b][g][f] = accW;
    g_pm[b][g][f] = accM;
    __threadfence();
    __syncthreads();
    if (f == 0) {
        ((volatile int*)g_flag)[blockIdx.x] = 1;
        for (int gg = g + 1; gg < G2; gg++)
            while (((volatile int*)g_flag)[(b << 6) | gg] == 0) {}
    }
    __syncthreads();
    float off = 0.f;
    for (int gg = g + 1; gg < G2; gg++) off += __ldcg(&g_pw[b][gg][f]);
    float acc = off;
    float* Sb = g_S + (size_t)(b * N + g * C2) * 128;
#pragma unroll 4
    for (int j = C2 - 1; j >= 0; j--) {
        acc = fmaf(sw[j], rows[j][f], acc);
        __stcg(&Sb[(size_t)j * 128 + f], acc);
    }
    if (g == 0) {
        float m = accM;
        for (int gg = 1; gg < G2; gg++) m += __ldcg(&g_pm[b][gg][f]);
        __stcg(&g_mean[b * 128 + f], m * (1.f / 2048.f));
    }
    // release: this chunk's S (and mean for g==0) done; wait for whole batch
    __threadfence();
    __syncthreads();
    if (f == 0) {
        ((volatile int*)g_flag2)[blockIdx.x] = 1;
        for (int gg = 0; gg < G2; gg++)
            while (((volatile int*)g_flag2)[(b << 6) | gg] == 0) {}
    }
    __syncthreads();

    // ---- output phase: this block serves rows i in [g*32, g*32+32) ----
    const float* ss = g_s2s + b * N;
#pragma unroll
    for (int r = 0; r < 8; r++) {
        const int i = g * C2 + warp * 8 + r;
        const float s1v = g_s1[b * N + i];
        bool p1 = (s1v + ss[lane * 64 + 63] > 0.f);
        unsigned m1 = __ballot_sync(0xFFFFFFFFu, p1);
        int lo;
        if (m1 == 0u) {
            lo = N;
        } else {
            int base = (__ffs(m1) - 1) * 64;
            bool p2 = (s1v + ss[base + lane * 2 + 1] > 0.f);
            unsigned m2 = __ballot_sync(0xFFFFFFFFu, p2);
            int cand = base + (__ffs(m2) - 1) * 2;
            lo = (s1v + ss[cand] > 0.f) ? cand : cand + 1;
        }
        float4 v;
        if (lo == N) {
            v = __ldcg(&((const float4*)(g_mean + b * 128))[lane]);
        } else {
            float invZ = 1.f / g_Z[b * (N + 1) + lo];
            float4 s = __ldcg(&((const float4*)(g_S + (size_t)(b * N + lo) * 128))[lane]);
            v = make_float4(s.x * invZ, s.y * invZ, s.z * invZ, s.w * invZ);
        }
        v.x = (v.x > 0.f) ? v.x : expm1f(v.x);
        v.y = (v.y > 0.f) ? v.y : expm1f(v.y);
        v.z = (v.z > 0.f) ? v.z : expm1f(v.z);
        v.w = (v.w > 0.f) ? v.w : expm1f(v.w);
        ((float4*)(out + (size_t)(b * N + i) * 128))[lane] = v;
    }
}

// ---------------- launch ----------------
extern "C" void kernel_launch(void* const* d_in, const int* in_sizes, int n_in,
                              void* d_out, int out_size) {
    const float* h = (const float*)d_in[0];   // [8,2048,128]
    const float* W = (const float*)d_in[1];   // [128,128]
    const float* a = (const float*)d_in[2];   // [256,1]
    float* out = (float*)d_out;

    gemm_kernel<<<BN / 128, 256>>>(h, W, a);
    sort_kernel<<<B, 1024>>>();
    scan_out_kernel<<<B * G2, 128>>>(out);
}

// round 14
// speedup vs baseline: 1.3212x; 1.3212x over previous
#include <cuda_runtime.h>
#include <math.h>

#define B 8
#define N 2048
#define F 128
#define BN (B*N)
#define G2 64          // chunks per batch (scan)
#define C2 32          // rows per chunk (G2*C2 == N)

// ---------------- scratch (device globals) ----------------
__device__ float g_Wh[BN * F];          // 8 MB
__device__ float g_s1[BN];
__device__ float g_s2[BN];
__device__ float g_s2s[BN];             // sorted s2 per batch (ascending)
__device__ int   g_perm[BN];
__device__ float g_w[BN];               // exp(s2s - max) per batch
__device__ float g_S[BN * F];           // suffix sums of w_j * Wh[perm[j],:]
__device__ float g_Z[B * (N + 1)];      // scalar suffix sums of w
__device__ float g_mean[B * F];
__device__ float g_pw[B][G2][F];        // chunk partial weighted sums
__device__ float g_pm[B][G2][F];        // chunk partial plain sums (for mean)
__device__ int   g_flag[B * G2];        // chunk-done flags (zeroed by sort_kernel)

// ---- Kernel 1: Wh = h @ W^T. 128x128 tile, 8x8/thread, k-major smem ----
#define SST 132
__global__ void __launch_bounds__(256, 1) gemm_kernel(const float* __restrict__ A,
                                                      const float* __restrict__ W,
                                                      const float* __restrict__ a) {
    __shared__ float AsT[16][SST];
    __shared__ float Bs[16][SST];
    __shared__ float sa[256];
    const int m0 = blockIdx.x * 128;
    const int tid = threadIdx.x;
    sa[tid] = a[tid];

    const int ty = tid >> 4;
    const int tx = tid & 15;

    float acc[8][8];
#pragma unroll
    for (int i = 0; i < 8; i++)
#pragma unroll
        for (int j = 0; j < 8; j++) acc[i][j] = 0.f;

    for (int k0 = 0; k0 < 128; k0 += 16) {
#pragma unroll
        for (int s = 0; s < 2; s++) {
            int q = tid + s * 256;
            int m = q >> 2;
            int kq = (q & 3) * 4;
            float4 av = *(const float4*)(A + (size_t)(m0 + m) * 128 + k0 + kq);
            AsT[kq + 0][m] = av.x; AsT[kq + 1][m] = av.y;
            AsT[kq + 2][m] = av.z; AsT[kq + 3][m] = av.w;
            float4 wv = *(const float4*)(W + (size_t)m * 128 + k0 + kq);
            Bs[kq + 0][m] = wv.x; Bs[kq + 1][m] = wv.y;
            Bs[kq + 2][m] = wv.z; Bs[kq + 3][m] = wv.w;
        }
        __syncthreads();
#pragma unroll
        for (int kk = 0; kk < 16; kk++) {
            float af[8], bf[8];
            *(float4*)&af[0] = *(const float4*)&AsT[kk][ty * 8];
            *(float4*)&af[4] = *(const float4*)&AsT[kk][ty * 8 + 4];
            *(float4*)&bf[0] = *(const float4*)&Bs[kk][tx * 8];
            *(float4*)&bf[4] = *(const float4*)&Bs[kk][tx * 8 + 4];
#pragma unroll
            for (int i = 0; i < 8; i++)
#pragma unroll
                for (int j = 0; j < 8; j++) acc[i][j] = fmaf(af[i], bf[j], acc[i][j]);
        }
        __syncthreads();
    }
#pragma unroll
    for (int i = 0; i < 8; i++) {
        const int m = m0 + ty * 8 + i;
        float* crow = g_Wh + (size_t)m * 128 + tx * 8;
        *(float4*)(crow + 0) = make_float4(acc[i][0], acc[i][1], acc[i][2], acc[i][3]);
        *(float4*)(crow + 4) = make_float4(acc[i][4], acc[i][5], acc[i][6], acc[i][7]);
        float p1 = 0.f, p2 = 0.f;
#pragma unroll
        for (int j = 0; j < 8; j++) {
            p1 = fmaf(acc[i][j], sa[tx * 8 + j], p1);
            p2 = fmaf(acc[i][j], sa[128 + tx * 8 + j], p2);
        }
#pragma unroll
        for (int o = 8; o; o >>= 1) {
            p1 += __shfl_down_sync(0xFFFFFFFFu, p1, o, 16);
            p2 += __shfl_down_sync(0xFFFFFFFFu, p2, o, 16);
        }
        if (tx == 0) { g_s1[m] = p1; g_s2[m] = p2; }
    }
}

// register-resident bitonic compare-exchange via warp shuffle (j <= 16)
__device__ __forceinline__ void bshuf(float& kv, int& iv, unsigned ei, int k, int j) {
    float pk = __shfl_xor_sync(0xFFFFFFFFu, kv, j);
    int   pi = __shfl_xor_sync(0xFFFFFFFFu, iv, j);
    bool lower = ((ei & (unsigned)j) == 0u);
    bool up    = ((ei & (unsigned)k) == 0u);
    float kl = lower ? kv : pk;
    float kh = lower ? pk : kv;
    bool sw = up ? (kl > kh) : (kl < kh);
    if (sw) { kv = pk; iv = pi; }
}

// ---- Kernel 2: per-batch bitonic sort of s2 (hybrid smem/warp) + w=exp + Z suffix ----
__global__ void __launch_bounds__(1024) sort_kernel() {
    __shared__ float key[2048];
    __shared__ int   idx[2048];
    __shared__ float alt[2048];
    const int b = blockIdx.x;
    const int t = threadIdx.x;
    if (t < G2) g_flag[b * G2 + t] = 0;

    float k0 = g_s2[b * N + t];
    float k1 = g_s2[b * N + t + 1024];
    int   i0 = t, i1 = t + 1024;
#pragma unroll
    for (int k = 2; k <= 32; k <<= 1)
#pragma unroll
        for (int j = k >> 1; j; j >>= 1) {
            bshuf(k0, i0, (unsigned)t, k, j);
            bshuf(k1, i1, (unsigned)(t + 1024), k, j);
        }
    key[t] = k0; idx[t] = i0;
    key[t + 1024] = k1; idx[t + 1024] = i1;
    __syncthreads();

    for (int k = 64; k <= 2048; k <<= 1) {
        for (int j = k >> 1; j >= 32; j >>= 1) {
            int i = ((t & ~(j - 1)) << 1) | (t & (j - 1));
            int p = i | j;
            bool up = ((i & k) == 0);
            float ki = key[i], kp = key[p];
            bool sw = up ? (ki > kp) : (ki < kp);
            if (sw) {
                key[i] = kp; key[p] = ki;
                int ii = idx[i]; idx[i] = idx[p]; idx[p] = ii;
            }
            __syncthreads();
        }
        k0 = key[t]; i0 = idx[t];
        k1 = key[t + 1024]; i1 = idx[t + 1024];
#pragma unroll
        for (int j = 16; j; j >>= 1) {
            bshuf(k0, i0, (unsigned)t, k, j);
            bshuf(k1, i1, (unsigned)(t + 1024), k, j);
        }
        key[t] = k0; idx[t] = i0;
        key[t + 1024] = k1; idx[t + 1024] = i1;
        __syncthreads();
    }

    g_s2s[b * N + t] = key[t];               g_perm[b * N + t] = idx[t];
    g_s2s[b * N + t + 1024] = key[t + 1024]; g_perm[b * N + t + 1024] = idx[t + 1024];

    const float mx = key[2047];
    __syncthreads();
    float w0 = expf(key[t] - mx);
    float w1 = expf(key[t + 1024] - mx);
    g_w[b * N + t] = w0;
    g_w[b * N + t + 1024] = w1;
    key[t] = w0; key[t + 1024] = w1;
    __syncthreads();
    float* src = key; float* dst = alt;
    for (int o = 1; o < 2048; o <<= 1) {
        dst[t]        = src[t] + ((t + o < 2048) ? src[t + o] : 0.f);
        dst[t + 1024] = src[t + 1024] + ((t + 1024 + o < 2048) ? src[t + 1024 + o] : 0.f);
        __syncthreads();
        float* tmp = src; src = dst; dst = tmp;
    }
    g_Z[b * (N + 1) + t] = src[t];
    g_Z[b * (N + 1) + t + 1024] = src[t + 1024];
    if (t == 0) g_Z[b * (N + 1) + 2048] = 0.f;
}

// ---- Kernel 3: fused chunk partial + PARALLEL lookback + suffix scan ----
// 512 blocks x 128 thr, 16.6KB smem: all co-resident in wave 1 -> spins are safe.
// Lookback: thread f polls flag g+1+f (one parallel L2 round trip), not a serial loop.
__global__ void __launch_bounds__(128) fused_scan_kernel() {
    const int b = blockIdx.x >> 6;
    const int g = blockIdx.x & (G2 - 1);
    const int f = threadIdx.x;
    __shared__ float rows[C2][F];
    __shared__ float sw[C2];
    __shared__ int   sp[C2];
    if (f < C2) {
        sw[f] = g_w[b * N + g * C2 + f];
        sp[f] = g_perm[b * N + g * C2 + f];
    }
    __syncthreads();
    const float* Whb = g_Wh + (size_t)b * N * 128;
    float accW = 0.f, accM = 0.f;
#pragma unroll 4
    for (int j = 0; j < C2; j++) {
        float x = Whb[(size_t)sp[j] * 128 + f];
        rows[j][f] = x;
        accW = fmaf(sw[j], x, accW);
        accM += x;
    }
    g_pw[b][g][f] = accW;
    g_pm[b][g][f] = accM;
    __threadfence();
    __syncthreads();
    if (f == 0) ((volatile int*)g_flag)[blockIdx.x] = 1;
    {   // parallel poll: thread f waits on flag for chunk g+1+f
        int gg = g + 1 + f;
        if (gg < G2)
            while (((volatile int*)g_flag)[(b << 6) | gg] == 0) {}
    }
    __syncthreads();
    __threadfence();

    // exclusive suffix offset across higher chunks (4-way MLP)
    float off = 0.f;
    {
        int gg = g + 1;
        for (; gg + 3 < G2; gg += 4) {
            float x0 = __ldcg(&g_pw[b][gg + 0][f]);
            float x1 = __ldcg(&g_pw[b][gg + 1][f]);
            float x2 = __ldcg(&g_pw[b][gg + 2][f]);
            float x3 = __ldcg(&g_pw[b][gg + 3][f]);
            off += (x0 + x1) + (x2 + x3);
        }
        for (; gg < G2; gg++) off += __ldcg(&g_pw[b][gg][f]);
    }
    float acc = off;
    float* Sb = g_S + (size_t)(b * N + g * C2) * 128;
#pragma unroll 4
    for (int j = C2 - 1; j >= 0; j--) {
        acc = fmaf(sw[j], rows[j][f], acc);
        __stcg(&Sb[(size_t)j * 128 + f], acc);
    }
    if (g == 0) {
        float m = accM;
        int gg = 1;
        for (; gg + 3 < G2; gg += 4) {
            float x0 = __ldcg(&g_pm[b][gg + 0][f]);
            float x1 = __ldcg(&g_pm[b][gg + 1][f]);
            float x2 = __ldcg(&g_pm[b][gg + 2][f]);
            float x3 = __ldcg(&g_pm[b][gg + 3][f]);
            m += (x0 + x1) + (x2 + x3);
        }
        for (; gg < G2; gg++) m += __ldcg(&g_pm[b][gg][f]);
        g_mean[b * 128 + f] = m * (1.f / 2048.f);
    }
}

// ---- Kernel 4: warp per row: 3-round lane-parallel ballot search + elu(S[k]/Z[k]) ----
__global__ void __launch_bounds__(256) out_kernel(float* __restrict__ out) {
    const int warp = threadIdx.x >> 5;
    const int lane = threadIdx.x & 31;
    const int row = blockIdx.x * 8 + warp;
    const int b = row >> 11;
    const float* ss = g_s2s + b * N;
    const float s1v = g_s1[row];

    bool p1 = (s1v + ss[lane * 64 + 63] > 0.f);
    unsigned m1 = __ballot_sync(0xFFFFFFFFu, p1);
    int lo;
    if (m1 == 0u) {
        lo = N;
    } else {
        int base = (__ffs(m1) - 1) * 64;
        bool p2 = (s1v + ss[base + lane * 2 + 1] > 0.f);
        unsigned m2 = __ballot_sync(0xFFFFFFFFu, p2);
        int cand = base + (__ffs(m2) - 1) * 2;
        lo = (s1v + ss[cand] > 0.f) ? cand : cand + 1;
    }

    float4 v;
    if (lo == N) {
        v = ((const float4*)(g_mean + b * 128))[lane];
    } else {
        float invZ = 1.f / g_Z[b * (N + 1) + lo];
        float4 s = __ldcg(&((const float4*)(g_S + (size_t)(b * N + lo) * 128))[lane]);
        v = make_float4(s.x * invZ, s.y * invZ, s.z * invZ, s.w * invZ);
    }
    v.x = (v.x > 0.f) ? v.x : expm1f(v.x);
    v.y = (v.y > 0.f) ? v.y : expm1f(v.y);
    v.z = (v.z > 0.f) ? v.z : expm1f(v.z);
    v.w = (v.w > 0.f) ? v.w : expm1f(v.w);
    ((float4*)(out + (size_t)row * 128))[lane] = v;
}

// ---------------- launch ----------------
extern "C" void kernel_launch(void* const* d_in, const int* in_sizes, int n_in,
                              void* d_out, int out_size) {
    const float* h = (const float*)d_in[0];   // [8,2048,128]
    const float* W = (const float*)d_in[1];   // [128,128]
    const float* a = (const float*)d_in[2];   // [256,1]
    float* out = (float*)d_out;

    gemm_kernel<<<BN / 128, 256>>>(h, W, a);
    sort_kernel<<<B, 1024>>>();
    fused_scan_kernel<<<B * G2, 128>>>();
    out_kernel<<<BN / 8, 256>>>(out);
}